// round 10
// baseline (speedup 1.0000x reference)
#include <cuda_runtime.h>
#include <cuda_fp16.h>
#include <cstdint>

// Problem constants (from reference)
#define B_      2
#define N_IN    163842
#define N_OUT   40962
#define C_      128
#define K_      7
#define INV_2SIG2 3.125f   // 1/(2*0.4^2)

// Scratch (allocation-free rule: __device__ globals).
// g_half holds UNNORMALIZED fp16 sums: row j = [b0 c0..127][b1 c0..127]
// = 256 halves = 512 contiguous bytes. Zeroed by memset nodes each call.
__device__ __half g_half[(size_t)N_OUT * 256];
__device__ float  g_denom[N_OUT];

// Bit-cast helpers (no SASS cost)
__device__ __forceinline__ unsigned h2_to_u(__half2 h) {
    unsigned u; *reinterpret_cast<__half2*>(&u) = h; return u;
}
__device__ __forceinline__ __half2 u_to_h2(unsigned u) {
    return *reinterpret_cast<__half2*>(&u);
}
__device__ __forceinline__ float4 ldcs_v4(const float4* p) {
    float4 v;
    asm volatile("ld.global.cs.v4.f32 {%0,%1,%2,%3}, [%4];"
                 : "=f"(v.x), "=f"(v.y), "=f"(v.z), "=f"(v.w) : "l"(p));
    return v;
}
__device__ __forceinline__ void stcs_v4(float4* p, float4 v) {
    asm volatile("st.global.cs.v4.f32 [%0], {%1,%2,%3,%4};"
                 :: "l"(p), "f"(v.x), "f"(v.y), "f"(v.z), "f"(v.w) : "memory");
}
// fp16x2 vector reduction, 16 bytes per op (sm_90+)
__device__ __forceinline__ void red_add_h2x4(__half* addr,
                                             __half2 a, __half2 b,
                                             __half2 c, __half2 d) {
    asm volatile("red.global.add.noftz.v4.f16x2 [%0], {%1, %2, %3, %4};"
                 :: "l"(addr), "r"(h2_to_u(a)), "r"(h2_to_u(b)),
                    "r"(h2_to_u(c)), "r"(h2_to_u(d)) : "memory");
}

// ---------------------------------------------------------------------------
// Kernel 1: scatter-add (fp16 accumulate, UNNORMALIZED)
//   g_half[parent[n], b, :] += fp16( omega[n] * x[b, n, :] )
//   g_denom[parent[n]]      += omega[n]
// TWO n per warp. Lane layout: lanes 0..15 = batch0 channels lane*8..+7,
// lanes 16..31 = batch1. One 16B red.v4.f16x2 per lane per n; 4 front-batched
// streaming x loads per lane (MLP=4). (Best measured config.)
// ---------------------------------------------------------------------------
__global__ void __launch_bounds__(256)
scatter_kernel(const float* __restrict__ x,
               const float* __restrict__ omega,
               const int*   __restrict__ parent)
{
    int w    = (blockIdx.x * blockDim.x + threadIdx.x) >> 5;
    int lane = threadIdx.x & 31;
    const int n0 = 2 * w;
    const int n1 = n0 + 1;
    if (n0 >= N_IN) return;   // N_IN even -> n1 also valid

    const int   p0  = __ldg(parent + n0);
    const int   p1  = __ldg(parent + n1);
    const float om0 = __ldg(omega + n0);
    const float om1 = __ldg(omega + n1);

    const int b   = lane >> 4;          // batch this lane owns
    const int ch8 = (lane & 15) * 8;    // starting channel (8 per lane)

    const float* base0 = x + (size_t)(b ? (N_IN + n0) : n0) * C_ + ch8;
    const float* base1 = x + (size_t)(b ? (N_IN + n1) : n1) * C_ + ch8;

    const float4 a0 = ldcs_v4(reinterpret_cast<const float4*>(base0));
    const float4 a1 = ldcs_v4(reinterpret_cast<const float4*>(base0 + 4));
    const float4 c0 = ldcs_v4(reinterpret_cast<const float4*>(base1));
    const float4 c1 = ldcs_v4(reinterpret_cast<const float4*>(base1 + 4));

    red_add_h2x4(g_half + (size_t)p0 * 256 + b * 128 + ch8,
                 __floats2half2_rn(a0.x * om0, a0.y * om0),
                 __floats2half2_rn(a0.z * om0, a0.w * om0),
                 __floats2half2_rn(a1.x * om0, a1.y * om0),
                 __floats2half2_rn(a1.z * om0, a1.w * om0));
    red_add_h2x4(g_half + (size_t)p1 * 256 + b * 128 + ch8,
                 __floats2half2_rn(c0.x * om1, c0.y * om1),
                 __floats2half2_rn(c0.z * om1, c0.w * om1),
                 __floats2half2_rn(c1.x * om1, c1.y * om1),
                 __floats2half2_rn(c1.z * om1, c1.w * om1));

    if (lane == 0) {
        atomicAdd(g_denom + p0, om0);
        atomicAdd(g_denom + p1, om1);
    }
}

// ---------------------------------------------------------------------------
// Kernel 2: gather  out[b,n,:] = sum_k coef_k * g_half[cand[n,k], b, :]
//   coef_k = w_k / ( clip(sum w) * clip(denom[j_k]) )   (normalization folded)
//   w_k = exp(-delta^2 * INV_2SIG2) * mask
// One warp per n; two independent LDG.64 per k (measured-best layout).
// Streaming stores keep g_half hot in L2. At the LTS cap — do not touch.
// ---------------------------------------------------------------------------
__global__ void __launch_bounds__(256)
gather_kernel(const float* __restrict__ delta,
              const float* __restrict__ mask,
              const int*   __restrict__ cand,
              float*       __restrict__ out)
{
    int w    = (blockIdx.x * blockDim.x + threadIdx.x) >> 5;
    int lane = threadIdx.x & 31;
    if (w >= N_IN) return;
    const int n = w;

    int   j  = 0;
    float e  = 0.f;
    float dn = 1.f;
    if (lane < K_) {
        const int idx = n * K_ + lane;
        j = __ldg(cand + idx);
        const float d = __ldg(delta + idx);
        e = __expf(-d * d * INV_2SIG2) * __ldg(mask + idx);
        const float* dptr = g_denom;
        dn = fmaxf(__ldg(dptr + j), 1e-8f);
    }

    float s = e;
    s += __shfl_xor_sync(0xffffffffu, s, 1);
    s += __shfl_xor_sync(0xffffffffu, s, 2);
    s += __shfl_xor_sync(0xffffffffu, s, 4);
    s  = __shfl_sync(0xffffffffu, s, 0);

    const float coef = e / (fmaxf(s, 1e-8f) * dn);  // lanes >= K_: e=0 -> 0

    float4 acc0 = make_float4(0.f, 0.f, 0.f, 0.f);
    float4 acc1 = make_float4(0.f, 0.f, 0.f, 0.f);

#pragma unroll
    for (int k = 0; k < K_; k++) {
        const int   jk = __shfl_sync(0xffffffffu, j,    k);
        const float ck = __shfl_sync(0xffffffffu, coef, k);
        const uint2* row = reinterpret_cast<const uint2*>(g_half + (size_t)jk * 256);
        const uint2 h0 = __ldg(row + lane);        // b0: channels lane*4..+3
        const uint2 h1 = __ldg(row + 32 + lane);   // b1

        const float2 f00 = __half22float2(u_to_h2(h0.x));
        const float2 f01 = __half22float2(u_to_h2(h0.y));
        const float2 f10 = __half22float2(u_to_h2(h1.x));
        const float2 f11 = __half22float2(u_to_h2(h1.y));

        acc0.x = fmaf(ck, f00.x, acc0.x); acc0.y = fmaf(ck, f00.y, acc0.y);
        acc0.z = fmaf(ck, f01.x, acc0.z); acc0.w = fmaf(ck, f01.y, acc0.w);
        acc1.x = fmaf(ck, f10.x, acc1.x); acc1.y = fmaf(ck, f10.y, acc1.y);
        acc1.z = fmaf(ck, f11.x, acc1.z); acc1.w = fmaf(ck, f11.y, acc1.w);
    }

    stcs_v4(reinterpret_cast<float4*>(out + (size_t)n * C_) + lane,          acc0);
    stcs_v4(reinterpret_cast<float4*>(out + (size_t)(N_IN + n) * C_) + lane, acc1);
}

// ---------------------------------------------------------------------------
// Launch
// Inputs (metadata order): 0=x, 1=omega, 2=delta, 3=cand_mask, 4=parent_idx,
//                          5=cand_idx. Output: float32 [B, N_IN, C].
// Zeroing is done with cudaMemsetAsync (captures as graph memset nodes —
// driver memset path beats a plain STG kernel, which is issue-bound at
// ~3.2 TB/s).
// ---------------------------------------------------------------------------
extern "C" void kernel_launch(void* const* d_in, const int* in_sizes, int n_in,
                              void* d_out, int out_size)
{
    const float* x      = (const float*)d_in[0];
    const float* omega  = (const float*)d_in[1];
    const float* delta  = (const float*)d_in[2];
    const float* mask   = (const float*)d_in[3];
    const int*   parent = (const int*)  d_in[4];
    const int*   cand   = (const int*)  d_in[5];
    float*       out    = (float*)d_out;

    void* half_ptr  = nullptr;
    void* denom_ptr = nullptr;
    cudaGetSymbolAddress(&half_ptr,  g_half);
    cudaGetSymbolAddress(&denom_ptr, g_denom);

    cudaMemsetAsync(half_ptr,  0, (size_t)N_OUT * 256 * sizeof(__half), 0);
    cudaMemsetAsync(denom_ptr, 0, (size_t)N_OUT * sizeof(float),        0);

    const int blocks_sc = ((N_IN / 2) * 32 + 255) / 256;   // two n per warp
    const int blocks_in = (N_IN * 32 + 255) / 256;         // one warp per n

    scatter_kernel<<<blocks_sc, 256>>>(x, omega, parent);
    gather_kernel<<<blocks_in, 256>>>(delta, mask, cand, out);
}

// round 12
// speedup vs baseline: 1.0440x; 1.0440x over previous
#include <cuda_runtime.h>
#include <cuda_fp16.h>
#include <cstdint>

// Problem constants (from reference)
#define B_      2
#define N_IN    163842
#define N_OUT   40962
#define C_      128
#define K_      7
#define INV_2SIG2 3.125f   // 1/(2*0.4^2)

// Scratch (allocation-free rule: __device__ globals).
// g_half holds UNNORMALIZED fp16 sums: row j = [b0 c0..127][b1 c0..127]
// = 256 halves = 512 contiguous bytes. Zeroed by zero_kernel each call.
__device__ __half g_half[(size_t)N_OUT * 256];
__device__ float  g_denom[N_OUT];

// Bit-cast helpers (no SASS cost)
__device__ __forceinline__ unsigned h2_to_u(__half2 h) {
    unsigned u; *reinterpret_cast<__half2*>(&u) = h; return u;
}
__device__ __forceinline__ __half2 u_to_h2(unsigned u) {
    return *reinterpret_cast<__half2*>(&u);
}
__device__ __forceinline__ float4 ldcs_v4(const float4* p) {
    float4 v;
    asm volatile("ld.global.cs.v4.f32 {%0,%1,%2,%3}, [%4];"
                 : "=f"(v.x), "=f"(v.y), "=f"(v.z), "=f"(v.w) : "l"(p));
    return v;
}
__device__ __forceinline__ void stcs_v4(float4* p, float4 v) {
    asm volatile("st.global.cs.v4.f32 [%0], {%1,%2,%3,%4};"
                 :: "l"(p), "f"(v.x), "f"(v.y), "f"(v.z), "f"(v.w) : "memory");
}
// fp16x2 vector reduction, 16 bytes per op (sm_90+)
__device__ __forceinline__ void red_add_h2x4(__half* addr,
                                             __half2 a, __half2 b,
                                             __half2 c, __half2 d) {
    asm volatile("red.global.add.noftz.v4.f16x2 [%0], {%1, %2, %3, %4};"
                 :: "l"(addr), "r"(h2_to_u(a)), "r"(h2_to_u(b)),
                    "r"(h2_to_u(c)), "r"(h2_to_u(d)) : "memory");
}

// ---------------------------------------------------------------------------
// Kernel 0: zero g_half (21 MB) + g_denom. (Measured: beats memset nodes.)
// ---------------------------------------------------------------------------
#define ZERO_N4 ((N_OUT * 256) / 8)          // uint4 slots in g_half
__global__ void zero_kernel() {
    int i = blockIdx.x * blockDim.x + threadIdx.x;
    if (i < ZERO_N4)
        reinterpret_cast<uint4*>(g_half)[i] = make_uint4(0u, 0u, 0u, 0u);
    if (i < N_OUT) g_denom[i] = 0.f;
}

// ---------------------------------------------------------------------------
// Kernel 1: scatter-add (fp16 accumulate, UNNORMALIZED)
//   g_half[parent[n], b, :] += fp16( omega[n] * x[b, n, :] )
//   g_denom[parent[n]]      += omega[n]
// TWO n per warp; lanes 0..15 = batch0 (8 ch each), 16..31 = batch1.
// One 16B red.v4.f16x2 per lane per n. (Best measured config — untouched.)
// ---------------------------------------------------------------------------
__global__ void __launch_bounds__(256)
scatter_kernel(const float* __restrict__ x,
               const float* __restrict__ omega,
               const int*   __restrict__ parent)
{
    int w    = (blockIdx.x * blockDim.x + threadIdx.x) >> 5;
    int lane = threadIdx.x & 31;
    const int n0 = 2 * w;
    const int n1 = n0 + 1;
    if (n0 >= N_IN) return;   // N_IN even -> n1 also valid

    const int   p0  = __ldg(parent + n0);
    const int   p1  = __ldg(parent + n1);
    const float om0 = __ldg(omega + n0);
    const float om1 = __ldg(omega + n1);

    const int b   = lane >> 4;          // batch this lane owns
    const int ch8 = (lane & 15) * 8;    // starting channel (8 per lane)

    const float* base0 = x + (size_t)(b ? (N_IN + n0) : n0) * C_ + ch8;
    const float* base1 = x + (size_t)(b ? (N_IN + n1) : n1) * C_ + ch8;

    const float4 a0 = ldcs_v4(reinterpret_cast<const float4*>(base0));
    const float4 a1 = ldcs_v4(reinterpret_cast<const float4*>(base0 + 4));
    const float4 c0 = ldcs_v4(reinterpret_cast<const float4*>(base1));
    const float4 c1 = ldcs_v4(reinterpret_cast<const float4*>(base1 + 4));

    red_add_h2x4(g_half + (size_t)p0 * 256 + b * 128 + ch8,
                 __floats2half2_rn(a0.x * om0, a0.y * om0),
                 __floats2half2_rn(a0.z * om0, a0.w * om0),
                 __floats2half2_rn(a1.x * om0, a1.y * om0),
                 __floats2half2_rn(a1.z * om0, a1.w * om0));
    red_add_h2x4(g_half + (size_t)p1 * 256 + b * 128 + ch8,
                 __floats2half2_rn(c0.x * om1, c0.y * om1),
                 __floats2half2_rn(c0.z * om1, c0.w * om1),
                 __floats2half2_rn(c1.x * om1, c1.y * om1),
                 __floats2half2_rn(c1.z * om1, c1.w * om1));

    if (lane == 0) {
        atomicAdd(g_denom + p0, om0);
        atomicAdd(g_denom + p1, om1);
    }
}

// ---------------------------------------------------------------------------
// Kernel 2: gather  out[b,n,:] = sum_k coef_k * g_half[cand[n,k], b, :]
//   coef_k = w_k / ( clip(sum w) * clip(denom[j_k]) )
// L1/issue-bound per ncu (L1=70.6%, issue=68.2%, L2 only 51%) -> this version
// precomputes all (row ptr, coef) pairs BEFORE the loop (hoists the 26-cyc
// shuffle chain off the load path) and software-pipelines the loads one k
// ahead so 4 LDG.64 stay in flight.
// ---------------------------------------------------------------------------
__global__ void __launch_bounds__(256)
gather_kernel(const float* __restrict__ delta,
              const float* __restrict__ mask,
              const int*   __restrict__ cand,
              float*       __restrict__ out)
{
    int w    = (blockIdx.x * blockDim.x + threadIdx.x) >> 5;
    int lane = threadIdx.x & 31;
    if (w >= N_IN) return;
    const int n = w;

    int   j  = 0;
    float e  = 0.f;
    float dn = 1.f;
    if (lane < K_) {
        const int idx = n * K_ + lane;
        j = __ldg(cand + idx);
        const float d = __ldg(delta + idx);
        e = __expf(-d * d * INV_2SIG2) * __ldg(mask + idx);
        const float* dptr = g_denom;
        dn = fmaxf(__ldg(dptr + j), 1e-8f);
    }

    float s = e;
    s += __shfl_xor_sync(0xffffffffu, s, 1);
    s += __shfl_xor_sync(0xffffffffu, s, 2);
    s += __shfl_xor_sync(0xffffffffu, s, 4);
    s  = __shfl_sync(0xffffffffu, s, 0);

    const float coef = e / (fmaxf(s, 1e-8f) * dn);  // lanes >= K_: e=0 -> 0

    // Precompute per-k row pointers + coefficients (pull shuffle latency
    // out of the load chain).
    const uint2* rows[K_];
    float        cks[K_];
#pragma unroll
    for (int k = 0; k < K_; k++) {
        const int jk = __shfl_sync(0xffffffffu, j, k);
        cks[k]  = __shfl_sync(0xffffffffu, coef, k);
        rows[k] = reinterpret_cast<const uint2*>(g_half + (size_t)jk * 256) + lane;
    }

    float4 acc0 = make_float4(0.f, 0.f, 0.f, 0.f);
    float4 acc1 = make_float4(0.f, 0.f, 0.f, 0.f);

    // Software-pipelined: loads for k+1 issued before FMAs of k.
    uint2 h0 = __ldg(rows[0]);
    uint2 h1 = __ldg(rows[0] + 32);
#pragma unroll
    for (int k = 0; k < K_; k++) {
        uint2 nh0, nh1;
        if (k + 1 < K_) {
            nh0 = __ldg(rows[k + 1]);
            nh1 = __ldg(rows[k + 1] + 32);
        }
        const float ck = cks[k];
        const float2 f00 = __half22float2(u_to_h2(h0.x));
        const float2 f01 = __half22float2(u_to_h2(h0.y));
        const float2 f10 = __half22float2(u_to_h2(h1.x));
        const float2 f11 = __half22float2(u_to_h2(h1.y));

        acc0.x = fmaf(ck, f00.x, acc0.x); acc0.y = fmaf(ck, f00.y, acc0.y);
        acc0.z = fmaf(ck, f01.x, acc0.z); acc0.w = fmaf(ck, f01.y, acc0.w);
        acc1.x = fmaf(ck, f10.x, acc1.x); acc1.y = fmaf(ck, f10.y, acc1.y);
        acc1.z = fmaf(ck, f11.x, acc1.z); acc1.w = fmaf(ck, f11.y, acc1.w);

        h0 = nh0;
        h1 = nh1;
    }

    stcs_v4(reinterpret_cast<float4*>(out + (size_t)n * C_) + lane,          acc0);
    stcs_v4(reinterpret_cast<float4*>(out + (size_t)(N_IN + n) * C_) + lane, acc1);
}

// ---------------------------------------------------------------------------
// Launch
// Inputs (metadata order): 0=x, 1=omega, 2=delta, 3=cand_mask, 4=parent_idx,
//                          5=cand_idx. Output: float32 [B, N_IN, C].
// ---------------------------------------------------------------------------
extern "C" void kernel_launch(void* const* d_in, const int* in_sizes, int n_in,
                              void* d_out, int out_size)
{
    const float* x      = (const float*)d_in[0];
    const float* omega  = (const float*)d_in[1];
    const float* delta  = (const float*)d_in[2];
    const float* mask   = (const float*)d_in[3];
    const int*   parent = (const int*)  d_in[4];
    const int*   cand   = (const int*)  d_in[5];
    float*       out    = (float*)d_out;

    const int blocks_z  = (ZERO_N4 + 255) / 256;           // one uint4/thread
    const int blocks_sc = ((N_IN / 2) * 32 + 255) / 256;   // two n per warp
    const int blocks_in = (N_IN * 32 + 255) / 256;         // one warp per n

    zero_kernel<<<blocks_z, 256>>>();
    scatter_kernel<<<blocks_sc, 256>>>(x, omega, parent);
    gather_kernel<<<blocks_in, 256>>>(delta, mask, cand, out);
}